// round 9
// baseline (speedup 1.0000x reference)
#include <cuda_runtime.h>
#include <cuda_fp16.h>
#include <cstdint>

#define OUT_F 11008
#define IN_F  4096
#define BATCH 32
#define GROUP 128

#define OB      256                  // M tile (8 warps x 32 rows)
#define OTILES  (OUT_F / OB)         // 43
#define KSPLIT  16
#define KRANGE  (IN_F / KSPLIT)      // 256
#define KC      128                  // chunk == GROUP (scale-rescale trick)
#define NCH     (KRANGE / KC)        // 2
#define THREADS 256
#define PWROW   (IN_F / 8)           // 512 words per output row

#define APITCH_B 80                  // A packed row pitch (64B data + 16 pad)
#define BPITCH_B 272                 // B row pitch (256B data + 16 pad)

// smem arena (bytes): A 2x20480, B 2x8704 = 58368
#define SA0 0
#define SA1 20480
#define SB0 40960
#define SB1 49664
#define SMTOT 58368

#define DQ_MASK  0x000f000fu
#define DQ_MAGIC 0x64086408u         // fp16x2 (1032, 1032)

__device__ __half g_xh[BATCH * IN_F];    // x fp16, k-permuted

__device__ __forceinline__ uint32_t smem_u32(const void* p) {
    uint32_t a;
    asm("{ .reg .u64 t; cvta.to.shared.u64 t, %1; cvt.u32.u64 %0, t; }"
        : "=r"(a) : "l"(p));
    return a;
}
__device__ __forceinline__ void ldsm4(uint32_t& r0, uint32_t& r1, uint32_t& r2,
                                      uint32_t& r3, uint32_t addr) {
    asm volatile("ldmatrix.sync.aligned.m8n8.x4.shared.b16 {%0,%1,%2,%3}, [%4];"
                 : "=r"(r0), "=r"(r1), "=r"(r2), "=r"(r3) : "r"(addr));
}
__device__ __forceinline__ void lds64(uint32_t& lo, uint32_t& hi, uint32_t addr) {
    asm volatile("ld.shared.v2.u32 {%0,%1}, [%2];" : "=r"(lo), "=r"(hi) : "r"(addr));
}
__device__ __forceinline__ void mma_f16(float* c,
                                        uint32_t a0, uint32_t a1, uint32_t a2,
                                        uint32_t a3, uint32_t b0, uint32_t b1) {
    asm volatile(
        "mma.sync.aligned.m16n8k16.row.col.f32.f16.f16.f32 "
        "{%0,%1,%2,%3}, {%4,%5,%6,%7}, {%8,%9}, {%0,%1,%2,%3};"
        : "+f"(c[0]), "+f"(c[1]), "+f"(c[2]), "+f"(c[3])
        : "r"(a0), "r"(a1), "r"(a2), "r"(a3), "r"(b0), "r"(b1));
}
__device__ __forceinline__ void cp16(uint32_t saddr, const void* gaddr) {
    asm volatile("cp.async.cg.shared.global [%0], [%1], 16;"
                 :: "r"(saddr), "l"(gaddr) : "memory");
}
// nibbles (c, c+4) of p -> f16x2 of exact signed int4 values
__device__ __forceinline__ uint32_t dqf(uint32_t p, int sh) {
    uint32_t r = ((p >> sh) & DQ_MASK) ^ DQ_MAGIC;
    const uint32_t mg = DQ_MAGIC;
    __half2 h = __hsub2(*reinterpret_cast<__half2*>(&r),
                        *reinterpret_cast<const __half2*>(&mg));
    return *reinterpret_cast<uint32_t*>(&h);
}

// ---------------- prep: x fp16 (k-permuted) + out = bias ----------------
__global__ void prep_kernel(const float* __restrict__ x,
                            const float* __restrict__ bias,
                            float* __restrict__ out) {
    int i = blockIdx.x * blockDim.x + threadIdx.x;
    if (i < BATCH * IN_F) {
        int b = i >> 12;
        int k = i & (IN_F - 1);
        int j = k & 7;
        int kp = (k & ~7) | ((j & 3) << 1) | (j >> 2);   // nibble j -> k-slot
        g_xh[b * IN_F + kp] = __float2half_rn(x[i]);
    }
    if (i < BATCH * OUT_F) out[i] = bias[i % OUT_F];
}

// ---------------- main: register-dequant HMMA GEMM, M32/warp ----------------
__global__ __launch_bounds__(THREADS, 3)
void wql_hmma_kernel(const int*   __restrict__ pw,
                     const float* __restrict__ scale,
                     float*       __restrict__ out) {
    extern __shared__ __align__(16) unsigned char dynsm[];
    const uint32_t smb = smem_u32(dynsm);

    const int tid   = threadIdx.x;
    const int wid   = tid >> 5;
    const int lane  = tid & 31;
    const int obase = blockIdx.x * OB;
    const int ks    = blockIdx.y;
    const int kbase = ks * KRANGE;

    const int sh = (lane & 3) * 4;            // dequant shift
    const int r0 = wid * 32 + (lane >> 2);    // warp rows r0, +8, +16, +24
    const uint32_t arow0 = r0 * APITCH_B;

    uint32_t boff[2];
#pragma unroll
    for (int nb = 0; nb < 2; ++nb)
        boff[nb] = (nb * 16 + ((lane >> 4) & 1) * 8 + (lane & 7)) * BPITCH_B
                 + ((lane >> 3) & 1) * 16;

    const uint32_t ab[2] = { smb + SA0, smb + SA1 };
    const uint32_t bb[2] = { smb + SB0, smb + SB1 };

    // staging roles
    const int brow = tid >> 3, bseg = tid & 7;   // B: 32 rows x 8x32B

    float acc[2][4][4];                          // [mfrag][n8frag][frag]
#pragma unroll
    for (int mf = 0; mf < 2; ++mf)
#pragma unroll
        for (int nf = 0; nf < 4; ++nf)
#pragma unroll
            for (int j = 0; j < 4; ++j) acc[mf][nf][j] = 0.f;

    // ---- stage chunk 0 ----
    {
        const int* asrc = &pw[(obase + tid) * PWROW + (kbase >> 3)];
        uint32_t adst = ab[0] + tid * APITCH_B;
#pragma unroll
        for (int v = 0; v < 4; ++v) cp16(adst + v * 16, asrc + v * 4);
        const __half* bsrc = &g_xh[brow * IN_F + kbase + bseg * 16];
        uint32_t bdst = bb[0] + brow * BPITCH_B + bseg * 32;
        cp16(bdst, bsrc); cp16(bdst + 16, bsrc + 8);
        asm volatile("cp.async.commit_group;" ::: "memory");
    }

    float s_prev[4] = {1.f, 1.f, 1.f, 1.f};

#pragma unroll
    for (int c = 0; c < NCH; ++c) {
        const int buf = c & 1;
        asm volatile("cp.async.wait_group 0;" ::: "memory");
        __syncthreads();

        // ---- prefetch chunk c+1 ----
        if (c + 1 < NCH) {
            const int k1 = kbase + (c + 1) * KC;
            const int* asrc = &pw[(obase + tid) * PWROW + (k1 >> 3)];
            uint32_t adst = ab[buf ^ 1] + tid * APITCH_B;
#pragma unroll
            for (int v = 0; v < 4; ++v) cp16(adst + v * 16, asrc + v * 4);
            const __half* bsrc = &g_xh[brow * IN_F + k1 + bseg * 16];
            uint32_t bdst = bb[buf ^ 1] + brow * BPITCH_B + bseg * 32;
            cp16(bdst, bsrc); cp16(bdst + 16, bsrc + 8);
            asm volatile("cp.async.commit_group;" ::: "memory");
        }

        // ---- rescale accumulators into this group's raw-int domain ----
        {
            const int gidx = ks * NCH + c;
            float s_cur[4];
#pragma unroll
            for (int rr = 0; rr < 4; ++rr)
                s_cur[rr] = __ldg(&scale[(obase + r0 + rr * 8) * (IN_F / GROUP) + gidx]);
            if (c) {
                float t[4];
#pragma unroll
                for (int rr = 0; rr < 4; ++rr)
                    t[rr] = __fdividef(s_prev[rr], s_cur[rr]);
#pragma unroll
                for (int mf = 0; mf < 2; ++mf)
#pragma unroll
                    for (int nf = 0; nf < 4; ++nf) {
                        acc[mf][nf][0] *= t[mf * 2];
                        acc[mf][nf][1] *= t[mf * 2];
                        acc[mf][nf][2] *= t[mf * 2 + 1];
                        acc[mf][nf][3] *= t[mf * 2 + 1];
                    }
            }
#pragma unroll
            for (int rr = 0; rr < 4; ++rr) s_prev[rr] = s_cur[rr];
        }

        // ---- compute: 8 k16 steps, A dequant in registers ----
#pragma unroll
        for (int s = 0; s < 8; ++s) {
            uint32_t pl[4], ph[4];
#pragma unroll
            for (int rr = 0; rr < 4; ++rr)
                lds64(pl[rr], ph[rr], ab[buf] + arow0 + rr * 8 * APITCH_B + s * 8);

            uint32_t b[8];
            ldsm4(b[0], b[1], b[2], b[3], bb[buf] + boff[0] + s * 32);
            ldsm4(b[4], b[5], b[6], b[7], bb[buf] + boff[1] + s * 32);

#pragma unroll
            for (int mf = 0; mf < 2; ++mf) {
                uint32_t a0 = dqf(pl[mf * 2], sh);
                uint32_t a1 = dqf(pl[mf * 2 + 1], sh);
                uint32_t a2 = dqf(ph[mf * 2], sh);
                uint32_t a3 = dqf(ph[mf * 2 + 1], sh);
#pragma unroll
                for (int nf = 0; nf < 4; ++nf)
                    mma_f16(acc[mf][nf], a0, a1, a2, a3, b[nf * 2], b[nf * 2 + 1]);
            }
        }
    }

    // ---- epilogue: final scale + atomics ----
#pragma unroll
    for (int mf = 0; mf < 2; ++mf) {
        const int orow = obase + r0 + mf * 16;
        const float sa = s_prev[mf * 2], sb = s_prev[mf * 2 + 1];
#pragma unroll
        for (int nf = 0; nf < 4; ++nf) {
            const int bcol = nf * 8 + (lane & 3) * 2;
            atomicAdd(&out[bcol * OUT_F + orow],           acc[mf][nf][0] * sa);
            atomicAdd(&out[(bcol + 1) * OUT_F + orow],     acc[mf][nf][1] * sa);
            atomicAdd(&out[bcol * OUT_F + orow + 8],       acc[mf][nf][2] * sb);
            atomicAdd(&out[(bcol + 1) * OUT_F + orow + 8], acc[mf][nf][3] * sb);
        }
    }
}

extern "C" void kernel_launch(void* const* d_in, const int* in_sizes, int n_in,
                              void* d_out, int out_size) {
    const float* x     = (const float*)d_in[0];
    const int*   pw    = (const int*)  d_in[1];
    const float* scale = (const float*)d_in[2];
    const float* bias  = (const float*)d_in[3];
    float* out = (float*)d_out;

    static int smem_set = 0;
    if (!smem_set) {
        cudaFuncSetAttribute(wql_hmma_kernel,
                             cudaFuncAttributeMaxDynamicSharedMemorySize, SMTOT);
        smem_set = 1;
    }

    prep_kernel<<<(BATCH * OUT_F + 255) / 256, 256>>>(x, bias, out);
    dim3 grid(OTILES, KSPLIT);
    wql_hmma_kernel<<<grid, THREADS, SMTOT>>>(pw, scale, out);
}

// round 11
// speedup vs baseline: 1.0769x; 1.0769x over previous
#include <cuda_runtime.h>
#include <cuda_fp16.h>
#include <cstdint>

#define OUT_F 11008
#define IN_F  4096
#define BATCH 32
#define GROUP 128

#define OB      128                  // M tile
#define OTILES  (OUT_F / OB)         // 86
#define KSPLIT  16
#define KRANGE  (IN_F / KSPLIT)      // 256
#define KC      128                  // chunk == GROUP (scale-rescale trick)
#define NCH     (KRANGE / KC)        // 2
#define THREADS 256
#define PWROW   (IN_F / 8)           // 512 words per output row

#define APITCH_B 80                  // A packed row pitch (64B data + 16 pad)
#define BPITCH_B 272                 // B row pitch (256B data + 16 pad)

// smem arena (bytes): A 2x10240, B 2x8704
#define SA0 0
#define SA1 10240
#define SB0 20480
#define SB1 29184
#define SMTOT 37888

#define DQ_MASK  0x000f000fu
#define DQ_MAGIC 0x64086408u         // fp16x2 (1032, 1032)

__device__ __half g_xh[BATCH * IN_F];    // x fp16, k-permuted

__device__ __forceinline__ uint32_t smem_u32(const void* p) {
    uint32_t a;
    asm("{ .reg .u64 t; cvta.to.shared.u64 t, %1; cvt.u32.u64 %0, t; }"
        : "=r"(a) : "l"(p));
    return a;
}
__device__ __forceinline__ void ldsm4(uint32_t& r0, uint32_t& r1, uint32_t& r2,
                                      uint32_t& r3, uint32_t addr) {
    asm volatile("ldmatrix.sync.aligned.m8n8.x4.shared.b16 {%0,%1,%2,%3}, [%4];"
                 : "=r"(r0), "=r"(r1), "=r"(r2), "=r"(r3) : "r"(addr));
}
__device__ __forceinline__ void lds64(uint32_t& lo, uint32_t& hi, uint32_t addr) {
    asm volatile("ld.shared.v2.u32 {%0,%1}, [%2];" : "=r"(lo), "=r"(hi) : "r"(addr));
}
__device__ __forceinline__ void mma_f16(float* c,
                                        uint32_t a0, uint32_t a1, uint32_t a2,
                                        uint32_t a3, uint32_t b0, uint32_t b1) {
    asm volatile(
        "mma.sync.aligned.m16n8k16.row.col.f32.f16.f16.f32 "
        "{%0,%1,%2,%3}, {%4,%5,%6,%7}, {%8,%9}, {%0,%1,%2,%3};"
        : "+f"(c[0]), "+f"(c[1]), "+f"(c[2]), "+f"(c[3])
        : "r"(a0), "r"(a1), "r"(a2), "r"(a3), "r"(b0), "r"(b1));
}
__device__ __forceinline__ void cp16(uint32_t saddr, const void* gaddr) {
    asm volatile("cp.async.cg.shared.global [%0], [%1], 16;"
                 :: "r"(saddr), "l"(gaddr) : "memory");
}
// nibbles (c, c+4) of p -> f16x2 of exact signed int4 values
__device__ __forceinline__ uint32_t dqf(uint32_t p, int sh) {
    uint32_t r = ((p >> sh) & DQ_MASK) ^ DQ_MAGIC;
    const uint32_t mg = DQ_MAGIC;
    __half2 h = __hsub2(*reinterpret_cast<__half2*>(&r),
                        *reinterpret_cast<const __half2*>(&mg));
    return *reinterpret_cast<uint32_t*>(&h);
}

// ---------------- prep: x fp16 (k-permuted) + out = bias (float4) ----------------
__global__ void prep_kernel(const float* __restrict__ x,
                            const float* __restrict__ bias,
                            float* __restrict__ out) {
    int i = blockIdx.x * blockDim.x + threadIdx.x;
    if (i < BATCH * IN_F) {
        int b = i >> 12;
        int k = i & (IN_F - 1);
        int j = k & 7;
        int kp = (k & ~7) | ((j & 3) << 1) | (j >> 2);   // nibble j -> k-slot
        g_xh[b * IN_F + kp] = __float2half_rn(x[i]);
    }
    if (i < BATCH * OUT_F / 4) {
        float4 b4 = *reinterpret_cast<const float4*>(&bias[(i * 4) % OUT_F]);
        reinterpret_cast<float4*>(out)[i] = b4;
    }
}

// ---------------- main: register-dequant HMMA GEMM, N=32, occ 5 ----------------
__global__ __launch_bounds__(THREADS, 5)
void wql_hmma_kernel(const int*   __restrict__ pw,
                     const float* __restrict__ scale,
                     float*       __restrict__ out) {
    extern __shared__ __align__(16) unsigned char dynsm[];
    const uint32_t smb = smem_u32(dynsm);

    const int tid   = threadIdx.x;
    const int wid   = tid >> 5;
    const int lane  = tid & 31;
    const int obase = blockIdx.x * OB;
    const int ks    = blockIdx.y;
    const int kbase = ks * KRANGE;

    const int sh = (lane & 3) * 4;           // dequant shift
    const int r0 = wid * 16 + (lane >> 2);   // A rows r0, r0+8

    // lean address bases (constant deltas folded as immediates)
    const uint32_t aoff = r0 * APITCH_B;     // row r0; +8*APITCH_B for r0+8
    const uint32_t boff = (((lane >> 4) & 1) * 8 + (lane & 7)) * BPITCH_B
                        + ((lane >> 3) & 1) * 16;   // nb0; +16*BPITCH_B for nb1

    // staging roles
    const int arow = tid >> 1, ahalf = tid & 1;   // A: 128 rows x 2x32B
    const int brow = tid >> 3, bseg = tid & 7;    // B: 32 rows x 8x32B

    float acc[4][4];
#pragma unroll
    for (int q = 0; q < 4; ++q)
#pragma unroll
        for (int j = 0; j < 4; ++j) acc[q][j] = 0.f;

    // ---- stage chunk 0 ----
    {
        const int* asrc = &pw[(obase + arow) * PWROW + (kbase >> 3) + ahalf * 8];
        uint32_t adst = smb + SA0 + arow * APITCH_B + ahalf * 32;
        cp16(adst, asrc); cp16(adst + 16, asrc + 4);
        const __half* bsrc = &g_xh[brow * IN_F + kbase + bseg * 16];
        uint32_t bdst = smb + SB0 + brow * BPITCH_B + bseg * 32;
        cp16(bdst, bsrc); cp16(bdst + 16, bsrc + 8);
        asm volatile("cp.async.commit_group;" ::: "memory");
    }

    float s_prev0 = 1.f, s_prev1 = 1.f;

#pragma unroll
    for (int c = 0; c < NCH; ++c) {
        const uint32_t ab = smb + (c & 1 ? SA1 : SA0);
        const uint32_t bb = smb + (c & 1 ? SB1 : SB0);
        asm volatile("cp.async.wait_group 0;" ::: "memory");
        __syncthreads();

        // ---- prefetch chunk c+1 into the other buffers ----
        if (c + 1 < NCH) {
            const int k1 = kbase + (c + 1) * KC;
            const int* asrc = &pw[(obase + arow) * PWROW + (k1 >> 3) + ahalf * 8];
            uint32_t adst = smb + ((c & 1) ? SA0 : SA1) + arow * APITCH_B + ahalf * 32;
            cp16(adst, asrc); cp16(adst + 16, asrc + 4);
            const __half* bsrc = &g_xh[brow * IN_F + k1 + bseg * 16];
            uint32_t bdst = smb + ((c & 1) ? SB0 : SB1) + brow * BPITCH_B + bseg * 32;
            cp16(bdst, bsrc); cp16(bdst + 16, bsrc + 8);
            asm volatile("cp.async.commit_group;" ::: "memory");
        }

        // ---- rescale accumulators into this group's raw-int domain ----
        {
            const int gidx = ks * NCH + c;
            float s_cur0 = __ldg(&scale[(obase + r0) * (IN_F / GROUP) + gidx]);
            float s_cur1 = __ldg(&scale[(obase + r0 + 8) * (IN_F / GROUP) + gidx]);
            if (c) {
                float t0 = __fdividef(s_prev0, s_cur0);
                float t1 = __fdividef(s_prev1, s_cur1);
#pragma unroll
                for (int q = 0; q < 4; ++q) {
                    acc[q][0] *= t0; acc[q][1] *= t0;
                    acc[q][2] *= t1; acc[q][3] *= t1;
                }
            }
            s_prev0 = s_cur0; s_prev1 = s_cur1;
        }

        // ---- compute: 8 k16 steps, A dequant in registers ----
#pragma unroll
        for (int s = 0; s < 8; ++s) {
            uint32_t p0l, p0h, p1l, p1h;
            lds64(p0l, p0h, ab + aoff + s * 8);
            lds64(p1l, p1h, ab + aoff + 8 * APITCH_B + s * 8);
            uint32_t a0 = dqf(p0l, sh), a2 = dqf(p0h, sh);
            uint32_t a1 = dqf(p1l, sh), a3 = dqf(p1h, sh);

            uint32_t b0, b1, b2, b3;
            ldsm4(b0, b1, b2, b3, bb + boff + s * 32);
            mma_f16(acc[0], a0, a1, a2, a3, b0, b1);
            mma_f16(acc[1], a0, a1, a2, a3, b2, b3);
            ldsm4(b0, b1, b2, b3, bb + boff + 16 * BPITCH_B + s * 32);
            mma_f16(acc[2], a0, a1, a2, a3, b0, b1);
            mma_f16(acc[3], a0, a1, a2, a3, b2, b3);
        }
    }

    // ---- epilogue: final scale + atomics ----
    const int orow0 = obase + r0;
#pragma unroll
    for (int q = 0; q < 4; ++q) {
        const int bcol = q * 8 + (lane & 3) * 2;
        atomicAdd(&out[bcol * OUT_F + orow0],           acc[q][0] * s_prev0);
        atomicAdd(&out[(bcol + 1) * OUT_F + orow0],     acc[q][1] * s_prev0);
        atomicAdd(&out[bcol * OUT_F + orow0 + 8],       acc[q][2] * s_prev1);
        atomicAdd(&out[(bcol + 1) * OUT_F + orow0 + 8], acc[q][3] * s_prev1);
    }
}

extern "C" void kernel_launch(void* const* d_in, const int* in_sizes, int n_in,
                              void* d_out, int out_size) {
    const float* x     = (const float*)d_in[0];
    const int*   pw    = (const int*)  d_in[1];
    const float* scale = (const float*)d_in[2];
    const float* bias  = (const float*)d_in[3];
    float* out = (float*)d_out;

    static int smem_set = 0;
    if (!smem_set) {
        cudaFuncSetAttribute(wql_hmma_kernel,
                             cudaFuncAttributeMaxDynamicSharedMemorySize, SMTOT);
        smem_set = 1;
    }

    prep_kernel<<<(BATCH * IN_F + 255) / 256, 256>>>(x, bias, out);
    dim3 grid(OTILES, KSPLIT);
    wql_hmma_kernel<<<grid, THREADS, SMTOT>>>(pw, scale, out);
}

// round 12
// speedup vs baseline: 1.0784x; 1.0014x over previous
#include <cuda_runtime.h>
#include <cuda_fp16.h>
#include <cstdint>

#define OUT_F 11008
#define IN_F  4096
#define BATCH 32
#define GROUP 128

#define OB      128                  // M tile
#define OTILES  (OUT_F / OB)         // 86
#define KSPLIT  8
#define KRANGE  (IN_F / KSPLIT)      // 512
#define KC      128                  // chunk == GROUP (scale-rescale trick)
#define NCH     (KRANGE / KC)        // 4
#define THREADS 256
#define PWROW   (IN_F / 8)           // 512 words per output row

#define APITCH_B 80                  // A packed row pitch (64B data + 16 pad)
#define BPITCH_B 272                 // B row pitch (256B data + 16 pad)

// smem arena (bytes): A 2x10240, B 2x8704
#define SA0 0
#define SA1 10240
#define SB0 20480
#define SB1 29184
#define SMTOT 37888

#define DQ_MASK  0x000f000fu
#define DQ_MAGIC 0x64086408u         // fp16x2 (1032, 1032)

__device__ __half g_xh[BATCH * IN_F];    // x fp16, k-permuted

__device__ __forceinline__ uint32_t smem_u32(const void* p) {
    uint32_t a;
    asm("{ .reg .u64 t; cvta.to.shared.u64 t, %1; cvt.u32.u64 %0, t; }"
        : "=r"(a) : "l"(p));
    return a;
}
__device__ __forceinline__ void ldsm4(uint32_t& r0, uint32_t& r1, uint32_t& r2,
                                      uint32_t& r3, uint32_t addr) {
    asm volatile("ldmatrix.sync.aligned.m8n8.x4.shared.b16 {%0,%1,%2,%3}, [%4];"
                 : "=r"(r0), "=r"(r1), "=r"(r2), "=r"(r3) : "r"(addr));
}
__device__ __forceinline__ void lds64(uint32_t& lo, uint32_t& hi, uint32_t addr) {
    asm volatile("ld.shared.v2.u32 {%0,%1}, [%2];" : "=r"(lo), "=r"(hi) : "r"(addr));
}
__device__ __forceinline__ void mma_f16(float* c,
                                        uint32_t a0, uint32_t a1, uint32_t a2,
                                        uint32_t a3, uint32_t b0, uint32_t b1) {
    asm volatile(
        "mma.sync.aligned.m16n8k16.row.col.f32.f16.f16.f32 "
        "{%0,%1,%2,%3}, {%4,%5,%6,%7}, {%8,%9}, {%0,%1,%2,%3};"
        : "+f"(c[0]), "+f"(c[1]), "+f"(c[2]), "+f"(c[3])
        : "r"(a0), "r"(a1), "r"(a2), "r"(a3), "r"(b0), "r"(b1));
}
__device__ __forceinline__ void cp16(uint32_t saddr, const void* gaddr) {
    asm volatile("cp.async.cg.shared.global [%0], [%1], 16;"
                 :: "r"(saddr), "l"(gaddr) : "memory");
}
// nibbles (c, c+4) of p -> f16x2 of exact signed int4 values
__device__ __forceinline__ uint32_t dqf(uint32_t p, int sh) {
    uint32_t r = ((p >> sh) & DQ_MASK) ^ DQ_MAGIC;
    const uint32_t mg = DQ_MAGIC;
    __half2 h = __hsub2(*reinterpret_cast<__half2*>(&r),
                        *reinterpret_cast<const __half2*>(&mg));
    return *reinterpret_cast<uint32_t*>(&h);
}

// ---------------- prep: x fp16 (k-permuted) + out = bias (float4) ----------------
__global__ void prep_kernel(const float* __restrict__ x,
                            const float* __restrict__ bias,
                            float* __restrict__ out) {
    int i = blockIdx.x * blockDim.x + threadIdx.x;
    if (i < BATCH * IN_F) {
        int b = i >> 12;
        int k = i & (IN_F - 1);
        int j = k & 7;
        int kp = (k & ~7) | ((j & 3) << 1) | (j >> 2);   // nibble j -> k-slot
        g_xh[b * IN_F + kp] = __float2half_rn(x[i]);
    }
    if (i < BATCH * OUT_F / 4) {
        float4 b4 = *reinterpret_cast<const float4*>(&bias[(i * 4) % OUT_F]);
        reinterpret_cast<float4*>(out)[i] = b4;
    }
}

// ---------------- main: register-dequant HMMA GEMM, single wave ----------------
__global__ __launch_bounds__(THREADS, 5)
void wql_hmma_kernel(const int*   __restrict__ pw,
                     const float* __restrict__ scale,
                     float*       __restrict__ out) {
    extern __shared__ __align__(16) unsigned char dynsm[];
    const uint32_t smb = smem_u32(dynsm);

    const int tid   = threadIdx.x;
    const int wid   = tid >> 5;
    const int lane  = tid & 31;
    const int obase = blockIdx.x * OB;
    const int ks    = blockIdx.y;
    const int kbase = ks * KRANGE;

    const int sh = (lane & 3) * 4;           // dequant shift
    const int r0 = wid * 16 + (lane >> 2);   // A rows r0, r0+8

    const uint32_t aoff = r0 * APITCH_B;
    const uint32_t boff = (((lane >> 4) & 1) * 8 + (lane & 7)) * BPITCH_B
                        + ((lane >> 3) & 1) * 16;

    // staging roles
    const int arow = tid >> 1, ahalf = tid & 1;   // A: 128 rows x 2x32B
    const int brow = tid >> 3, bseg = tid & 7;    // B: 32 rows x 8x32B

    float acc[4][4];
#pragma unroll
    for (int q = 0; q < 4; ++q)
#pragma unroll
        for (int j = 0; j < 4; ++j) acc[q][j] = 0.f;

    // ---- stage chunk 0 ----
    {
        const int* asrc = &pw[(obase + arow) * PWROW + (kbase >> 3) + ahalf * 8];
        uint32_t adst = smb + SA0 + arow * APITCH_B + ahalf * 32;
        cp16(adst, asrc); cp16(adst + 16, asrc + 4);
        const __half* bsrc = &g_xh[brow * IN_F + kbase + bseg * 16];
        uint32_t bdst = smb + SB0 + brow * BPITCH_B + bseg * 32;
        cp16(bdst, bsrc); cp16(bdst + 16, bsrc + 8);
        asm volatile("cp.async.commit_group;" ::: "memory");
    }

    float s_prev0 = 1.f, s_prev1 = 1.f;

#pragma unroll
    for (int c = 0; c < NCH; ++c) {
        const uint32_t ab = smb + ((c & 1) ? SA1 : SA0);
        const uint32_t bb = smb + ((c & 1) ? SB1 : SB0);
        asm volatile("cp.async.wait_group 0;" ::: "memory");
        __syncthreads();

        // ---- prefetch chunk c+1 into the other buffers ----
        if (c + 1 < NCH) {
            const int k1 = kbase + (c + 1) * KC;
            const int* asrc = &pw[(obase + arow) * PWROW + (k1 >> 3) + ahalf * 8];
            uint32_t adst = smb + ((c & 1) ? SA0 : SA1) + arow * APITCH_B + ahalf * 32;
            cp16(adst, asrc); cp16(adst + 16, asrc + 4);
            const __half* bsrc = &g_xh[brow * IN_F + k1 + bseg * 16];
            uint32_t bdst = smb + ((c & 1) ? SB0 : SB1) + brow * BPITCH_B + bseg * 32;
            cp16(bdst, bsrc); cp16(bdst + 16, bsrc + 8);
            asm volatile("cp.async.commit_group;" ::: "memory");
        }

        // ---- rescale accumulators into this group's raw-int domain ----
        {
            const int gidx = ks * NCH + c;
            float s_cur0 = __ldg(&scale[(obase + r0) * (IN_F / GROUP) + gidx]);
            float s_cur1 = __ldg(&scale[(obase + r0 + 8) * (IN_F / GROUP) + gidx]);
            if (c) {
                float t0 = __fdividef(s_prev0, s_cur0);
                float t1 = __fdividef(s_prev1, s_cur1);
#pragma unroll
                for (int q = 0; q < 4; ++q) {
                    acc[q][0] *= t0; acc[q][1] *= t0;
                    acc[q][2] *= t1; acc[q][3] *= t1;
                }
            }
            s_prev0 = s_cur0; s_prev1 = s_cur1;
        }

        // ---- compute: 8 k16 steps, A dequant in registers ----
#pragma unroll
        for (int s = 0; s < 8; ++s) {
            uint32_t p0l, p0h, p1l, p1h;
            lds64(p0l, p0h, ab + aoff + s * 8);
            lds64(p1l, p1h, ab + aoff + 8 * APITCH_B + s * 8);
            uint32_t a0 = dqf(p0l, sh), a2 = dqf(p0h, sh);
            uint32_t a1 = dqf(p1l, sh), a3 = dqf(p1h, sh);

            uint32_t b0, b1, b2, b3;
            ldsm4(b0, b1, b2, b3, bb + boff + s * 32);
            mma_f16(acc[0], a0, a1, a2, a3, b0, b1);
            mma_f16(acc[1], a0, a1, a2, a3, b2, b3);
            ldsm4(b0, b1, b2, b3, bb + boff + 16 * BPITCH_B + s * 32);
            mma_f16(acc[2], a0, a1, a2, a3, b0, b1);
            mma_f16(acc[3], a0, a1, a2, a3, b2, b3);
        }
    }

    // ---- epilogue: final scale + atomics ----
    const int orow0 = obase + r0;
#pragma unroll
    for (int q = 0; q < 4; ++q) {
        const int bcol = q * 8 + (lane & 3) * 2;
        atomicAdd(&out[bcol * OUT_F + orow0],           acc[q][0] * s_prev0);
        atomicAdd(&out[(bcol + 1) * OUT_F + orow0],     acc[q][1] * s_prev0);
        atomicAdd(&out[bcol * OUT_F + orow0 + 8],       acc[q][2] * s_prev1);
        atomicAdd(&out[(bcol + 1) * OUT_F + orow0 + 8], acc[q][3] * s_prev1);
    }
}

extern "C" void kernel_launch(void* const* d_in, const int* in_sizes, int n_in,
                              void* d_out, int out_size) {
    const float* x     = (const float*)d_in[0];
    const int*   pw    = (const int*)  d_in[1];
    const float* scale = (const float*)d_in[2];
    const float* bias  = (const float*)d_in[3];
    float* out = (float*)d_out;

    static int smem_set = 0;
    if (!smem_set) {
        cudaFuncSetAttribute(wql_hmma_kernel,
                             cudaFuncAttributeMaxDynamicSharedMemorySize, SMTOT);
        smem_set = 1;
    }

    prep_kernel<<<(BATCH * IN_F + 255) / 256, 256>>>(x, bias, out);
    dim3 grid(OTILES, KSPLIT);
    wql_hmma_kernel<<<grid, THREADS, SMTOT>>>(pw, scale, out);
}

// round 13
// speedup vs baseline: 1.0889x; 1.0097x over previous
#include <cuda_runtime.h>
#include <cuda_fp16.h>
#include <cstdint>

#define OUT_F 11008
#define IN_F  4096
#define BATCH 32
#define GROUP 128

#define OB      128                  // M tile
#define OTILES  (OUT_F / OB)         // 86
#define KSPLIT  16
#define KRANGE  (IN_F / KSPLIT)      // 256
#define KC      128                  // chunk == GROUP (scale-rescale trick)
#define NCH     (KRANGE / KC)        // 2
#define THREADS 256
#define PWROW   (IN_F / 8)           // 512 words per output row

#define APITCH_B 80                  // A packed row pitch (64B data + 16 pad)
#define BPITCH_B 272                 // B row pitch (256B data + 16 pad)

// smem arena (bytes): A 2x10240, B 2x8704
#define SA0 0
#define SA1 10240
#define SB0 20480
#define SB1 29184
#define SMTOT 37888

#define DQ_MASK  0x000f000fu
#define DQ_MAGIC 0x64086408u         // fp16x2 (1032, 1032)

__device__ __half g_xh[BATCH * IN_F];    // x fp16, k-permuted

__device__ __forceinline__ uint32_t smem_u32(const void* p) {
    uint32_t a;
    asm("{ .reg .u64 t; cvta.to.shared.u64 t, %1; cvt.u32.u64 %0, t; }"
        : "=r"(a) : "l"(p));
    return a;
}
__device__ __forceinline__ void ldsm4(uint32_t& r0, uint32_t& r1, uint32_t& r2,
                                      uint32_t& r3, uint32_t addr) {
    asm volatile("ldmatrix.sync.aligned.m8n8.x4.shared.b16 {%0,%1,%2,%3}, [%4];"
                 : "=r"(r0), "=r"(r1), "=r"(r2), "=r"(r3) : "r"(addr));
}
__device__ __forceinline__ void lds128(uint32_t& x, uint32_t& y, uint32_t& z,
                                       uint32_t& w, uint32_t addr) {
    asm volatile("ld.shared.v4.u32 {%0,%1,%2,%3}, [%4];"
                 : "=r"(x), "=r"(y), "=r"(z), "=r"(w) : "r"(addr));
}
__device__ __forceinline__ void mma_f16(float* c,
                                        uint32_t a0, uint32_t a1, uint32_t a2,
                                        uint32_t a3, uint32_t b0, uint32_t b1) {
    asm volatile(
        "mma.sync.aligned.m16n8k16.row.col.f32.f16.f16.f32 "
        "{%0,%1,%2,%3}, {%4,%5,%6,%7}, {%8,%9}, {%0,%1,%2,%3};"
        : "+f"(c[0]), "+f"(c[1]), "+f"(c[2]), "+f"(c[3])
        : "r"(a0), "r"(a1), "r"(a2), "r"(a3), "r"(b0), "r"(b1));
}
__device__ __forceinline__ void cp16(uint32_t saddr, const void* gaddr) {
    asm volatile("cp.async.cg.shared.global [%0], [%1], 16;"
                 :: "r"(saddr), "l"(gaddr) : "memory");
}
// nibbles (c, c+4) of p -> f16x2 of exact signed int4 values
__device__ __forceinline__ uint32_t dqf(uint32_t p, int sh) {
    uint32_t r = ((p >> sh) & DQ_MASK) ^ DQ_MAGIC;
    const uint32_t mg = DQ_MAGIC;
    __half2 h = __hsub2(*reinterpret_cast<__half2*>(&r),
                        *reinterpret_cast<const __half2*>(&mg));
    return *reinterpret_cast<uint32_t*>(&h);
}

// ---------------- prep: x fp16 (k-permuted) + out = bias (float4) ----------------
__global__ void prep_kernel(const float* __restrict__ x,
                            const float* __restrict__ bias,
                            float* __restrict__ out) {
    int i = blockIdx.x * blockDim.x + threadIdx.x;
    if (i < BATCH * IN_F) {
        int b = i >> 12;
        int k = i & (IN_F - 1);
        int j = k & 7;
        int kp = (k & ~7) | ((j & 3) << 1) | (j >> 2);   // nibble j -> k-slot
        g_xh[b * IN_F + kp] = __float2half_rn(x[i]);
    }
    if (i < BATCH * OUT_F / 4) {
        float4 b4 = *reinterpret_cast<const float4*>(&bias[(i * 4) % OUT_F]);
        reinterpret_cast<float4*>(out)[i] = b4;
    }
}

// ---------------- main: reg-resident-A HMMA GEMM ----------------
__global__ __launch_bounds__(THREADS, 4)
void wql_hmma_kernel(const int*   __restrict__ pw,
                     const float* __restrict__ scale,
                     float*       __restrict__ out) {
    extern __shared__ __align__(16) unsigned char dynsm[];
    const uint32_t smb = smem_u32(dynsm);

    const int tid   = threadIdx.x;
    const int wid   = tid >> 5;
    const int lane  = tid & 31;
    const int obase = blockIdx.x * OB;
    const int ks    = blockIdx.y;
    const int kbase = ks * KRANGE;

    const int sh = (lane & 3) * 4;           // dequant shift
    const int r0 = wid * 16 + (lane >> 2);   // A rows r0, r0+8

    const uint32_t aoff = r0 * APITCH_B;
    const uint32_t boff = (((lane >> 4) & 1) * 8 + (lane & 7)) * BPITCH_B
                        + ((lane >> 3) & 1) * 16;

    // staging roles
    const int arow = tid >> 1, ahalf = tid & 1;   // A: 128 rows x 2x32B
    const int brow = tid >> 3, bseg = tid & 7;    // B: 32 rows x 8x32B

    float acc[4][4];
#pragma unroll
    for (int q = 0; q < 4; ++q)
#pragma unroll
        for (int j = 0; j < 4; ++j) acc[q][j] = 0.f;

    // ---- stage chunk 0 ----
    {
        const int* asrc = &pw[(obase + arow) * PWROW + (kbase >> 3) + ahalf * 8];
        uint32_t adst = smb + SA0 + arow * APITCH_B + ahalf * 32;
        cp16(adst, asrc); cp16(adst + 16, asrc + 4);
        const __half* bsrc = &g_xh[brow * IN_F + kbase + bseg * 16];
        uint32_t bdst = smb + SB0 + brow * BPITCH_B + bseg * 32;
        cp16(bdst, bsrc); cp16(bdst + 16, bsrc + 8);
        asm volatile("cp.async.commit_group;" ::: "memory");
    }

    float s_prev0 = 1.f, s_prev1 = 1.f;

#pragma unroll
    for (int c = 0; c < NCH; ++c) {
        const uint32_t ab = smb + (c ? SA1 : SA0);
        const uint32_t bb = smb + (c ? SB1 : SB0);
        asm volatile("cp.async.wait_group 0;" ::: "memory");
        __syncthreads();

        // ---- prefetch chunk c+1 into the other buffers ----
        if (c + 1 < NCH) {
            const int k1 = kbase + (c + 1) * KC;
            const int* asrc = &pw[(obase + arow) * PWROW + (k1 >> 3) + ahalf * 8];
            uint32_t adst = smb + SA1 + arow * APITCH_B + ahalf * 32;
            cp16(adst, asrc); cp16(adst + 16, asrc + 4);
            const __half* bsrc = &g_xh[brow * IN_F + k1 + bseg * 16];
            uint32_t bdst = smb + SB1 + brow * BPITCH_B + bseg * 32;
            cp16(bdst, bsrc); cp16(bdst + 16, bsrc + 8);
            asm volatile("cp.async.commit_group;" ::: "memory");
        }

        // ---- rescale accumulators into this group's raw-int domain ----
        {
            const int gidx = ks * NCH + c;
            float s_cur0 = __ldg(&scale[(obase + r0) * (IN_F / GROUP) + gidx]);
            float s_cur1 = __ldg(&scale[(obase + r0 + 8) * (IN_F / GROUP) + gidx]);
            if (c) {
                float t0 = __fdividef(s_prev0, s_cur0);
                float t1 = __fdividef(s_prev1, s_cur1);
#pragma unroll
                for (int q = 0; q < 4; ++q) {
                    acc[q][0] *= t0; acc[q][1] *= t0;
                    acc[q][2] *= t1; acc[q][3] *= t1;
                }
            }
            s_prev0 = s_cur0; s_prev1 = s_cur1;
        }

        // ---- compute: 2 half-chunks of 4 k16 steps; A words register-resident ----
#pragma unroll
        for (int h = 0; h < 2; ++h) {
            uint32_t ra[8], rb[8];   // row r0 words 8h..8h+7, row r0+8 same
            lds128(ra[0], ra[1], ra[2], ra[3], ab + aoff + h * 32);
            lds128(ra[4], ra[5], ra[6], ra[7], ab + aoff + h * 32 + 16);
            lds128(rb[0], rb[1], rb[2], rb[3], ab + aoff + 8 * APITCH_B + h * 32);
            lds128(rb[4], rb[5], rb[6], rb[7], ab + aoff + 8 * APITCH_B + h * 32 + 16);

#pragma unroll
            for (int s2 = 0; s2 < 4; ++s2) {
                const int s = h * 4 + s2;
                uint32_t a0 = dqf(ra[2 * s2], sh);
                uint32_t a2 = dqf(ra[2 * s2 + 1], sh);
                uint32_t a1 = dqf(rb[2 * s2], sh);
                uint32_t a3 = dqf(rb[2 * s2 + 1], sh);

                uint32_t b0, b1, b2, b3;
                ldsm4(b0, b1, b2, b3, bb + boff + s * 32);
                mma_f16(acc[0], a0, a1, a2, a3, b0, b1);
                mma_f16(acc[1], a0, a1, a2, a3, b2, b3);
                ldsm4(b0, b1, b2, b3, bb + boff + 16 * BPITCH_B + s * 32);
                mma_f16(acc[2], a0, a1, a2, a3, b0, b1);
                mma_f16(acc[3], a0, a1, a2, a3, b2, b3);
            }
        }
    }

    // ---- epilogue: final scale + atomics ----
    const int orow0 = obase + r0;
#pragma unroll
    for (int q = 0; q < 4; ++q) {
        const int bcol = q * 8 + (lane & 3) * 2;
        atomicAdd(&out[bcol * OUT_F + orow0],           acc[q][0] * s_prev0);
        atomicAdd(&out[(bcol + 1) * OUT_F + orow0],     acc[q][1] * s_prev0);
        atomicAdd(&out[bcol * OUT_F + orow0 + 8],       acc[q][2] * s_prev1);
        atomicAdd(&out[(bcol + 1) * OUT_F + orow0 + 8], acc[q][3] * s_prev1);
    }
}

extern "C" void kernel_launch(void* const* d_in, const int* in_sizes, int n_in,
                              void* d_out, int out_size) {
    const float* x     = (const float*)d_in[0];
    const int*   pw    = (const int*)  d_in[1];
    const float* scale = (const float*)d_in[2];
    const float* bias  = (const float*)d_in[3];
    float* out = (float*)d_out;

    static int smem_set = 0;
    if (!smem_set) {
        cudaFuncSetAttribute(wql_hmma_kernel,
                             cudaFuncAttributeMaxDynamicSharedMemorySize, SMTOT);
        smem_set = 1;
    }

    prep_kernel<<<(BATCH * IN_F + 255) / 256, 256>>>(x, bias, out);
    dim3 grid(OTILES, KSPLIT);
    wql_hmma_kernel<<<grid, THREADS, SMTOT>>>(pw, scale, out);
}